// round 16
// baseline (speedup 1.0000x reference)
#include <cuda_runtime.h>
#include <cuda_fp16.h>
#include <stdint.h>

// LegoConv2d GB300 — R15: R12 base (94us) + epilogue surgery + 8x2 warp grid.
// fp16 1-term mma.sync GEMM per slab (b,h): feat[256 x 64] = X^T @ lego,
// fp32 accum, permuted K (k = chunk*48 + tap*16 + c16), 2 CTAs/SM.
// NEW vs R12: (1) branch-free float2 epilogue with fused int2 tables
// (idx premultiplied + coef), 14 iters; (2) warp tile 32x32 (4 ldmatrix
// per k-step instead of 5). Staging/MMA core otherwise identical to R12.

#define NCTA   304
#define NSLABS 608
#define FT_S   260            // feat row stride (f32), conflict-free dump

// smem byte offsets (per CTA, 100352 B total -> 2 CTAs/SM)
#define SM_XB0 0              // X buf0: 256 rows x 56 fp16 (stride 112B) = 28672
#define SM_XB1 28672
#define SM_LG  66560          // lego: 64 n x 200 fp16 (stride 400B) = 25600
#define SM_TAB 92160          // int2[1024]: {idx*260 + i*64, coef bits}
#define SM_SZ  100352
// feat (f32 64 x FT_S = 66560 B) overlays both X buffers [0, 66560)

__device__ __forceinline__ uint32_t smem_u32(const void* p) {
    uint32_t a;
    asm("{ .reg .u64 t; cvta.to.shared.u64 t, %1; cvt.u32.u64 %0, t; }" : "=r"(a) : "l"(p));
    return a;
}
__device__ __forceinline__ void ldmx4(uint32_t* r, uint32_t addr) {
    asm volatile("ldmatrix.sync.aligned.m8n8.x4.shared.b16 {%0,%1,%2,%3}, [%4];"
                 : "=r"(r[0]), "=r"(r[1]), "=r"(r[2]), "=r"(r[3]) : "r"(addr));
}
__device__ __forceinline__ void mma_fp16(float* d, const uint32_t* a,
                                         uint32_t b0, uint32_t b1) {
    asm volatile(
        "mma.sync.aligned.m16n8k16.row.col.f32.f16.f16.f32 "
        "{%0,%1,%2,%3}, {%4,%5,%6,%7}, {%8,%9}, {%0,%1,%2,%3};"
        : "+f"(d[0]), "+f"(d[1]), "+f"(d[2]), "+f"(d[3])
        : "r"(a[0]), "r"(a[1]), "r"(a[2]), "r"(a[3]), "r"(b0), "r"(b1));
}
__device__ __forceinline__ uint32_t pkh2(float lo, float hi) {
    __half2 h = __floats2half2_rn(lo, hi);
    return *(uint32_t*)&h;
}

extern __shared__ char smem[];

__global__ __launch_bounds__(512, 2)
void main_kernel(const float* __restrict__ x,
                 const float* __restrict__ lego,
                 const float* __restrict__ coefs,
                 const float* __restrict__ comb,
                 float* __restrict__ out)
{
    const int t = threadIdx.x, lane = t & 31, wid = t >> 5;
    const uint32_t sb = smem_u32(smem);

    int2* tab = (int2*)(smem + SM_TAB);   // [o*4 + i]

    // ---- fused prep: warp-parallel first-max argmax; fused table:
    //      tab[o*4+i] = { idx*FT_S + i*64  (feat float offset), coef bits }
    for (int row = wid * 64; row < wid * 64 + 64; row++) {
        float v = comb[(size_t)row * 64 + lane];
        int   i = lane;
        {
            float v2 = comb[(size_t)row * 64 + 32 + lane];
            if (v2 > v) { v = v2; i = lane + 32; }
        }
        #pragma unroll
        for (int off = 16; off; off >>= 1) {
            float ov = __shfl_xor_sync(0xFFFFFFFFu, v, off);
            int   oi = __shfl_xor_sync(0xFFFFFFFFu, i, off);
            if (ov > v || (ov == v && oi < i)) { v = ov; i = oi; }
        }
        if (lane == 0) {
            const int o = row & 255, sp = row >> 8;      // row = sp*256 + o
            tab[o * 4 + sp] = make_int2(
                i * FT_S + sp * 64,
                __float_as_int(coefs[(size_t)row * 64 + i]));
        }
    }

    // ---- stage lego fp16 once, K-permuted: k = (c>>4)*48 + tap*16 + (c&15)
    {
        __half* lg = (__half*)(smem + SM_LG);
        for (int s = t; s < 64 * 192; s += 512) {
            int n = s / 192, r = s - n * 192, c = r / 3, tap = r - c * 3;
            int k = (c >> 4) * 48 + tap * 16 + (c & 15);
            lg[n * 200 + k] = __float2half_rn(lego[s]);
        }
    }
    __syncthreads();

    const int wm = wid & 7, wn = wid >> 3;      // warp grid 8(M) x 2(N), 32x32 tile
    const int r  = lane >> 2, cq = lane & 3;

    // ldmatrix lane base addresses (A stride 112B, B stride 400B — proven)
    const uint32_t a_base = sb +
        (uint32_t)((wm * 32 + (lane & 15)) * 112 + (lane >> 4) * 16);
    const uint32_t b_base = sb + SM_LG +
        (uint32_t)((wn * 32 + 8 * ((lane >> 4) & 1) + (lane & 7)) * 400 +
                   16 * ((lane >> 3) & 1));

    float* feat = (float*)smem;

    // staging role: thread owns A row (merged col) = t&255, channel-half t>>8
    const int  srow = t & 255, shalf = t >> 8;
    const int  si = srow >> 6, sw = srow & 63;
    const bool valid = (sw < 56);
    char* xs_base = smem + srow * 112 + shalf * 16;   // + buf + tap*32

    for (int slab = blockIdx.x; slab < NSLABS; slab += NCTA) {
        const int h = slab % 19, b = slab / 19;
        const int y0 = 3 * h - 1;

        float d[2][4][4];
        #pragma unroll
        for (int jm = 0; jm < 2; jm++)
            #pragma unroll
            for (int jn = 0; jn < 4; jn++)
                #pragma unroll
                for (int q = 0; q < 4; q++) d[jm][jn][q] = 0.f;

        for (int chunk = 0; chunk < 4; chunk++) {
            const int buf = chunk & 1;

            // ---- stage X chunk: per tap, 8 channel planes -> one STS.128
            {
                const float* xb = x + ((size_t)(b * 256 + si * 64 +
                                    chunk * 16 + shalf * 8) * 56) * 56 + sw;
                char* xdst = xs_base + buf * 28672;
                #pragma unroll
                for (int tap = 0; tap < 3; tap++) {
                    const int y = y0 + tap;
                    float v[8];
                    if (valid && y >= 0) {
                        #pragma unroll
                        for (int j = 0; j < 8; j++) v[j] = xb[j * 3136 + y * 56];
                    } else {
                        #pragma unroll
                        for (int j = 0; j < 8; j++) v[j] = 0.f;
                    }
                    uint4 p;
                    p.x = pkh2(v[0], v[1]); p.y = pkh2(v[2], v[3]);
                    p.z = pkh2(v[4], v[5]); p.w = pkh2(v[6], v[7]);
                    *(uint4*)(xdst + tap * 32) = p;
                }
            }
            __syncthreads();

            // ---- MMA over chunk: 3 k16-steps; 2 B + 2 A ldmatrix, 8 mma
            #pragma unroll
            for (int ks = 0; ks < 3; ks++) {
                uint32_t bfr[8];
                ldmx4(bfr,     b_base + chunk * 96 + ks * 32);
                ldmx4(bfr + 4, b_base + 6400 + chunk * 96 + ks * 32);
                #pragma unroll
                for (int jm = 0; jm < 2; jm++) {
                    uint32_t afr[4];
                    ldmx4(afr, a_base + buf * 28672 + jm * 1792 + ks * 32);
                    mma_fp16(d[jm][0], afr, bfr[0], bfr[1]);
                    mma_fp16(d[jm][1], afr, bfr[2], bfr[3]);
                    mma_fp16(d[jm][2], afr, bfr[4], bfr[5]);
                    mma_fp16(d[jm][3], afr, bfr[6], bfr[7]);
                }
            }
        }
        __syncthreads();   // all MMAs done; feat overlays X buffers

        // ---- dump D -> feat[n][m]  (bank = 8cq + r: perfect permutation)
        #pragma unroll
        for (int jm = 0; jm < 2; jm++)
            #pragma unroll
            for (int jn = 0; jn < 4; jn++) {
                const int m0 = wm * 32 + 16 * jm + r;
                const int n0 = wn * 32 + 8 * jn + 2 * cq;
                feat[n0 * FT_S + m0]           = d[jm][jn][0];
                feat[(n0 + 1) * FT_S + m0]     = d[jm][jn][1];
                feat[n0 * FT_S + m0 + 8]       = d[jm][jn][2];
                feat[(n0 + 1) * FT_S + m0 + 8] = d[jm][jn][3];
            }
        __syncthreads();

        // ---- branch-free float2 epilogue: g = o*28 + p, w = 2p
        //      out[b,o,h,2p+1..2p+2] = sum_i cf*feat2[tab.x + 2p]
        {
            float* ob = out + ((size_t)(b * 256) * 19 + h) * 58;
            #pragma unroll
            for (int j = 0; j < 14; j++) {
                const int g = j * 512 + t;
                const int o = g / 28;
                const int p2 = (g - o * 28) * 2;
                const int2* tp = tab + o * 4;
                float a0 = 0.f, a1 = 0.f;
                #pragma unroll
                for (int i = 0; i < 4; i++) {
                    const int2 e = tp[i];
                    const float cf = __int_as_float(e.y);
                    const float2 f = *(const float2*)(feat + e.x + p2);
                    a0 = fmaf(cf, f.x, a0);
                    a1 = fmaf(cf, f.y, a1);
                }
                float* op = ob + o * 1102 + p2 + 1;
                op[0] = a0; op[1] = a1;
            }
            // exact-zero borders w=0, w=57
            const int oo = t >> 1, ww = (t & 1) ? 57 : 0;
            ob[oo * 1102 + ww] = 0.f;
        }
        __syncthreads();   // feat fully read before next slab's STS
    }
}

extern "C" void kernel_launch(void* const* d_in, const int* in_sizes, int n_in,
                              void* d_out, int out_size) {
    const float* x     = (const float*)d_in[0];   // 32*256*56*56
    const float* lego  = (const float*)d_in[1];   // 64*64*3*1
    const float* coefs = (const float*)d_in[2];   // 4*256*64
    const float* comb  = (const float*)d_in[3];   // 4*256*64
    float* out = (float*)d_out;                   // 32*256*19*58
    (void)in_sizes; (void)n_in; (void)out_size;

    cudaFuncSetAttribute(main_kernel,
                         cudaFuncAttributeMaxDynamicSharedMemorySize, SM_SZ);
    main_kernel<<<NCTA, 512, SM_SZ>>>(x, lego, coefs, comb, out);
}

// round 17
// speedup vs baseline: 1.3198x; 1.3198x over previous
#include <cuda_runtime.h>
#include <cuda_fp16.h>
#include <stdint.h>

// LegoConv2d GB300 — R16: byte-exact R12 core (94us) + split-barrier halves.
// fp16 1-term mma.sync GEMM per slab (b,h): feat[256 x 64] = X^T @ lego,
// fp32 accum, permuted K (k = chunk*48 + tap*16 + c16), 2 CTAs/SM.
// ONLY change vs R12: the CTA's 16 warps form two independent 256-thread
// halves (half h owns A rows [128h,128h+128)); per-chunk sync is a named
// bar.sync per half, so halves run out of phase and hide each other's
// staging stalls. Full __syncthreads only around the shared feat phase.

#define NCTA   304
#define NSLABS 608
#define FT_S   260            // feat row stride (f32), conflict-free dump

// smem byte offsets (per CTA, 100352 B total -> 2 CTAs/SM)
#define SM_XB0 0              // X buf0: 256 rows x 56 fp16 (stride 112B) = 28672
#define SM_XB1 28672
#define SM_LG  66560          // lego: 64 n x 200 fp16 (stride 400B) = 25600
#define SM_ID  92160          // int[1024]
#define SM_CF  96256          // float[1024]
#define SM_SZ  100352
// feat (f32 64 x FT_S = 66560 B) overlays both X buffers [0, 66560)

__device__ __forceinline__ uint32_t smem_u32(const void* p) {
    uint32_t a;
    asm("{ .reg .u64 t; cvta.to.shared.u64 t, %1; cvt.u32.u64 %0, t; }" : "=r"(a) : "l"(p));
    return a;
}
__device__ __forceinline__ void ldmx4(uint32_t* r, uint32_t addr) {
    asm volatile("ldmatrix.sync.aligned.m8n8.x4.shared.b16 {%0,%1,%2,%3}, [%4];"
                 : "=r"(r[0]), "=r"(r[1]), "=r"(r[2]), "=r"(r[3]) : "r"(addr));
}
__device__ __forceinline__ void mma_fp16(float* d, const uint32_t* a,
                                         uint32_t b0, uint32_t b1) {
    asm volatile(
        "mma.sync.aligned.m16n8k16.row.col.f32.f16.f16.f32 "
        "{%0,%1,%2,%3}, {%4,%5,%6,%7}, {%8,%9}, {%0,%1,%2,%3};"
        : "+f"(d[0]), "+f"(d[1]), "+f"(d[2]), "+f"(d[3])
        : "r"(a[0]), "r"(a[1]), "r"(a[2]), "r"(a[3]), "r"(b0), "r"(b1));
}
__device__ __forceinline__ uint32_t pkh2(float lo, float hi) {
    __half2 h = __floats2half2_rn(lo, hi);
    return *(uint32_t*)&h;
}
__device__ __forceinline__ void half_bar(int id) {
    asm volatile("bar.sync %0, %1;" :: "r"(id), "r"(256) : "memory");
}

extern __shared__ char smem[];

__global__ __launch_bounds__(512, 2)
void main_kernel(const float* __restrict__ x,
                 const float* __restrict__ lego,
                 const float* __restrict__ coefs,
                 const float* __restrict__ comb,
                 float* __restrict__ out)
{
    const int t = threadIdx.x, lane = t & 31, wid = t >> 5;
    const uint32_t sb = smem_u32(smem);

    int*   idx_s  = (int*)(smem + SM_ID);
    float* coef_s = (float*)(smem + SM_CF);

    // ---- fused prep: warp-parallel first-max argmax + coefficient pick
    for (int row = wid * 64; row < wid * 64 + 64; row++) {
        float v = comb[(size_t)row * 64 + lane];
        int   i = lane;
        {
            float v2 = comb[(size_t)row * 64 + 32 + lane];
            if (v2 > v) { v = v2; i = lane + 32; }
        }
        #pragma unroll
        for (int off = 16; off; off >>= 1) {
            float ov = __shfl_xor_sync(0xFFFFFFFFu, v, off);
            int   oi = __shfl_xor_sync(0xFFFFFFFFu, i, off);
            if (ov > v || (ov == v && oi < i)) { v = ov; i = oi; }
        }
        if (lane == 0) {
            idx_s[row]  = i;
            coef_s[row] = coefs[(size_t)row * 64 + i];
        }
    }

    // ---- stage lego fp16 once, K-permuted: k = (c>>4)*48 + tap*16 + (c&15)
    {
        __half* lg = (__half*)(smem + SM_LG);
        for (int s = t; s < 64 * 192; s += 512) {
            int n = s / 192, r = s - n * 192, c = r / 3, tap = r - c * 3;
            int k = (c >> 4) * 48 + tap * 16 + (c & 15);
            lg[n * 200 + k] = __float2half_rn(lego[s]);
        }
    }
    __syncthreads();

    // half h owns A rows [128h, 128h+128); within half: 2(M) x 4(N) warp grid
    const int hfl  = wid >> 3;                  // 0 or 1
    const int wid7 = wid & 7;
    const int wm = 2 * hfl + (wid7 & 1);        // 0..3 — same 64x16 tiles as R12
    const int wn = wid7 >> 1;                   // 0..3
    const int r  = lane >> 2, cq = lane & 3;

    // ldmatrix lane base addresses (A stride 112B, B stride 400B — proven)
    const uint32_t a_base = sb +
        (uint32_t)((wm * 64 + (lane & 15)) * 112 + (lane >> 4) * 16);
    const uint32_t b_base = sb + SM_LG +
        (uint32_t)((wn * 16 + 8 * ((lane >> 4) & 1) + (lane & 7)) * 400 +
                   16 * ((lane >> 3) & 1));

    float* feat = (float*)smem;

    // staging role: thread owns A row within its half; k-half = (t>>7)&1
    const int  srow = hfl * 128 + (t & 127), shalf = (t >> 7) & 1;
    const int  si = srow >> 6, sw = srow & 63;
    const bool valid = (sw < 56);
    char* xs_base = smem + srow * 112 + shalf * 16;   // + buf + tap*32

    for (int slab = blockIdx.x; slab < NSLABS; slab += NCTA) {
        const int h = slab % 19, b = slab / 19;
        const int y0 = 3 * h - 1;

        float d[4][2][4];
        #pragma unroll
        for (int jm = 0; jm < 4; jm++)
            #pragma unroll
            for (int jn = 0; jn < 2; jn++)
                #pragma unroll
                for (int q = 0; q < 4; q++) d[jm][jn][q] = 0.f;

        for (int chunk = 0; chunk < 4; chunk++) {
            const int buf = chunk & 1;

            // ---- stage X chunk (own half's rows): 8 planes -> one STS.128/tap
            {
                const float* xb = x + ((size_t)(b * 256 + si * 64 +
                                    chunk * 16 + shalf * 8) * 56) * 56 + sw;
                char* xdst = xs_base + buf * 28672;
                #pragma unroll
                for (int tap = 0; tap < 3; tap++) {
                    const int y = y0 + tap;
                    float v[8];
                    if (valid && y >= 0) {
                        #pragma unroll
                        for (int j = 0; j < 8; j++) v[j] = xb[j * 3136 + y * 56];
                    } else {
                        #pragma unroll
                        for (int j = 0; j < 8; j++) v[j] = 0.f;
                    }
                    uint4 p;
                    p.x = pkh2(v[0], v[1]); p.y = pkh2(v[2], v[3]);
                    p.z = pkh2(v[4], v[5]); p.w = pkh2(v[6], v[7]);
                    *(uint4*)(xdst + tap * 32) = p;
                }
            }
            half_bar(1 + hfl);     // only this half's rows are involved

            // ---- MMA over chunk: 3 k16-steps (ks == tap in permuted K)
            #pragma unroll
            for (int ks = 0; ks < 3; ks++) {
                uint32_t bfr[4];
                ldmx4(bfr, b_base + chunk * 96 + ks * 32);
                #pragma unroll
                for (int jm = 0; jm < 4; jm++) {
                    uint32_t afr[4];
                    ldmx4(afr, a_base + buf * 28672 + jm * 1792 + ks * 32);
                    mma_fp16(d[jm][0], afr, bfr[0], bfr[1]);
                    mma_fp16(d[jm][1], afr, bfr[2], bfr[3]);
                }
            }
        }
        __syncthreads();   // halves rejoin: all MMAs done; feat overlays X bufs

        // ---- dump D -> feat[n][m]  (identical pattern to R12)
        #pragma unroll
        for (int jm = 0; jm < 4; jm++)
            #pragma unroll
            for (int jn = 0; jn < 2; jn++) {
                const int m0 = wm * 64 + 16 * jm + r;
                const int n0 = wn * 16 + 8 * jn + 2 * cq;
                feat[n0 * FT_S + m0]           = d[jm][jn][0];
                feat[(n0 + 1) * FT_S + m0]     = d[jm][jn][1];
                feat[n0 * FT_S + m0 + 8]       = d[jm][jn][2];
                feat[(n0 + 1) * FT_S + m0 + 8] = d[jm][jn][3];
            }
        __syncthreads();

        // ---- epilogue (R12-proven): out[b,o,h,w+1] = sum_i cf*feat[idx][i*64+w]
        {
            float* ob = out + ((size_t)(b * 256) * 19 + h) * 58;
            int o = t / 56, w = t - o * 56;
            #pragma unroll 4
            for (int it = 0; it < 28; it++) {
                float acc = 0.f;
                #pragma unroll
                for (int i = 0; i < 4; i++) {
                    const int   id = idx_s[i * 256 + o];
                    const float cf = coef_s[i * 256 + o];
                    acc = fmaf(cf, feat[id * FT_S + i * 64 + w], acc);
                }
                ob[o * 1102 + w + 1] = acc;
                o += 9; w += 8;
                if (w >= 56) { w -= 56; o += 1; }
            }
            // exact-zero borders w=0, w=57
            const int oo = t >> 1, ww = (t & 1) ? 57 : 0;
            ob[oo * 1102 + ww] = 0.f;
        }
        __syncthreads();   // feat fully read before next slab's STS
    }
}

extern "C" void kernel_launch(void* const* d_in, const int* in_sizes, int n_in,
                              void* d_out, int out_size) {
    const float* x     = (const float*)d_in[0];   // 32*256*56*56
    const float* lego  = (const float*)d_in[1];   // 64*64*3*1
    const float* coefs = (const float*)d_in[2];   // 4*256*64
    const float* comb  = (const float*)d_in[3];   // 4*256*64
    float* out = (float*)d_out;                   // 32*256*19*58
    (void)in_sizes; (void)n_in; (void)out_size;

    cudaFuncSetAttribute(main_kernel,
                         cudaFuncAttributeMaxDynamicSharedMemorySize, SM_SZ);
    main_kernel<<<NCTA, 512, SM_SZ>>>(x, lego, coefs, comb, out);
}